// round 1
// baseline (speedup 1.0000x reference)
#include <cuda_runtime.h>

#define Hd   64
#define Wd   64
#define HW   4096
#define Bd   4
#define Cd   256
#define COd  256
#define Kd   9
#define KDIM 2304    // Cd * 9
#define NTOT 16384   // Bd * HW
#define NGRP 16
#define CPG  16      // COd / NGRP

// 151 MB scratch for im2col columns: cols[(c*9+k)][n], n = b*4096 + hw
__device__ float g_cols[KDIM * NTOT];
// per (b, group): mean, rsqrt(var+eps)
__device__ float g_stats[Bd * NGRP * 2];

// ---------------------------------------------------------------------------
// Kernel 1: deformable bilinear sampling -> cols
// grid: (NTOT/256, 9), block: 256. One thread = one (k, n); loops over c.
// ---------------------------------------------------------------------------
__global__ __launch_bounds__(256) void sample_kernel(
    const float* __restrict__ in,      // [B, C, H, W]
    const float* __restrict__ off,     // [B, 18, H, W]
    const float* __restrict__ mask)    // [B, 9, H, W]
{
    const int n  = blockIdx.x * 256 + threadIdx.x;   // 0..16383
    const int k  = blockIdx.y;                        // 0..8
    const int b  = n >> 12;
    const int hw = n & 4095;
    const int h  = hw >> 6;
    const int w  = hw & 63;

    const float dy = off[((b * 18 + 2 * k)     << 12) + hw];
    const float dx = off[((b * 18 + 2 * k + 1) << 12) + hw];
    const float m  = mask[((b * 9 + k)         << 12) + hw];

    const float y = (float)h + (float)(k / 3 - 1) + dy;
    const float x = (float)w + (float)(k % 3 - 1) + dx;

    const float y0f = floorf(y);
    const float x0f = floorf(x);
    const int   y0  = (int)y0f;
    const int   x0  = (int)x0f;
    const float wy1 = y - y0f;
    const float wx1 = x - x0f;
    const float wy0 = 1.0f - wy1;
    const float wx0 = 1.0f - wx1;

    const bool vy0 = (y0     >= 0) && (y0     < Hd);
    const bool vy1 = (y0 + 1 >= 0) && (y0 + 1 < Hd);
    const bool vx0 = (x0     >= 0) && (x0     < Wd);
    const bool vx1 = (x0 + 1 >= 0) && (x0 + 1 < Wd);

    // weights folded with validity and mask
    const float w00 = (vy0 && vx0) ? wy0 * wx0 * m : 0.0f;
    const float w01 = (vy0 && vx1) ? wy0 * wx1 * m : 0.0f;
    const float w10 = (vy1 && vx0) ? wy1 * wx0 * m : 0.0f;
    const float w11 = (vy1 && vx1) ? wy1 * wx1 * m : 0.0f;

    // safe in-plane indices (0 when invalid; weight already 0)
    const int i00 = (vy0 && vx0) ? (y0       * Wd + x0    ) : 0;
    const int i01 = (vy0 && vx1) ? (y0       * Wd + x0 + 1) : 0;
    const int i10 = (vy1 && vx0) ? ((y0 + 1) * Wd + x0    ) : 0;
    const int i11 = (vy1 && vx1) ? ((y0 + 1) * Wd + x0 + 1) : 0;

    const float* __restrict__ p = in + (size_t)(b * Cd) * HW;
    float* __restrict__ outp = g_cols + (size_t)k * NTOT + n;

#pragma unroll 4
    for (int c = 0; c < Cd; ++c) {
        const float* pc = p + c * HW;
        float v = w00 * __ldg(pc + i00)
                + w01 * __ldg(pc + i01)
                + w10 * __ldg(pc + i10)
                + w11 * __ldg(pc + i11);
        outp[(size_t)(c * 9) * NTOT] = v;
    }
}

// ---------------------------------------------------------------------------
// Kernel 2: fp32 GEMM  out[m, n] = sum_k W[m, k] * cols[k, n]  (+bias)
// M = 256, N = 16384, K = 2304. 128x128 tile, BK=16, 256 thr, 8x8 per thread.
// ---------------------------------------------------------------------------
#define BM 128
#define BN 128
#define BK 16

__global__ __launch_bounds__(256) void gemm_kernel(
    const float* __restrict__ Wt,     // [256, 2304] (= weight[o][c][3][3])
    const float* __restrict__ bias,   // [256]
    float* __restrict__ out)          // [B, Co, H, W]
{
    __shared__ float As[BK][BM];
    __shared__ float Bs[BK][BN];

    const int tid = threadIdx.x;
    const int tx  = tid & 15;
    const int ty  = tid >> 4;
    const int n0  = blockIdx.x * BN;
    const int m0  = blockIdx.y * BM;

    float acc[8][8];
#pragma unroll
    for (int i = 0; i < 8; ++i)
#pragma unroll
        for (int j = 0; j < 8; ++j) acc[i][j] = 0.0f;

    // A loader: thread -> (row = tid>>1, 8 cols starting at (tid&1)*8)
    const int arow  = tid >> 1;
    const int ahalf = (tid & 1) * 8;
    // B loader: thread -> (row = tid>>4, 8 cols starting at (tid&15)*8)
    const int brow = tid >> 4;
    const int bcol = (tid & 15) * 8;

    const float* aptr = Wt + (size_t)(m0 + arow) * KDIM + ahalf;
    const float* bptr = g_cols + (size_t)brow * NTOT + n0 + bcol;

    for (int k0 = 0; k0 < KDIM; k0 += BK) {
        float4 a0 = *(const float4*)(aptr + k0);
        float4 a1 = *(const float4*)(aptr + k0 + 4);
        As[ahalf + 0][arow] = a0.x;
        As[ahalf + 1][arow] = a0.y;
        As[ahalf + 2][arow] = a0.z;
        As[ahalf + 3][arow] = a0.w;
        As[ahalf + 4][arow] = a1.x;
        As[ahalf + 5][arow] = a1.y;
        As[ahalf + 6][arow] = a1.z;
        As[ahalf + 7][arow] = a1.w;

        const float* bp = bptr + (size_t)k0 * NTOT;
        float4 b0 = *(const float4*)(bp);
        float4 b1 = *(const float4*)(bp + 4);
        *(float4*)&Bs[brow][bcol]     = b0;
        *(float4*)&Bs[brow][bcol + 4] = b1;

        __syncthreads();

#pragma unroll
        for (int kk = 0; kk < BK; ++kk) {
            float af[8], bf[8];
            *(float4*)(af)     = *(const float4*)&As[kk][ty * 8];
            *(float4*)(af + 4) = *(const float4*)&As[kk][ty * 8 + 4];
            *(float4*)(bf)     = *(const float4*)&Bs[kk][tx * 8];
            *(float4*)(bf + 4) = *(const float4*)&Bs[kk][tx * 8 + 4];
#pragma unroll
            for (int i = 0; i < 8; ++i)
#pragma unroll
                for (int j = 0; j < 8; ++j)
                    acc[i][j] += af[i] * bf[j];
        }
        __syncthreads();
    }

    // epilogue: add bias, write to out[b][o][hw]. n-tile never crosses b.
    const int b   = n0 >> 12;
    const int hw0 = (n0 & 4095) + tx * 8;
#pragma unroll
    for (int i = 0; i < 8; ++i) {
        const int o  = m0 + ty * 8 + i;
        const float bi = bias[o];
        float* po = out + ((size_t)(b * COd + o) << 12) + hw0;
        float4 v0, v1;
        v0.x = acc[i][0] + bi; v0.y = acc[i][1] + bi;
        v0.z = acc[i][2] + bi; v0.w = acc[i][3] + bi;
        v1.x = acc[i][4] + bi; v1.y = acc[i][5] + bi;
        v1.z = acc[i][6] + bi; v1.w = acc[i][7] + bi;
        *(float4*)(po)     = v0;
        *(float4*)(po + 4) = v1;
    }
}

// ---------------------------------------------------------------------------
// Kernel 3: GroupNorm stats per (b, group): deterministic block reduction
// grid: 64 blocks (b*16+g), block: 256 threads
// ---------------------------------------------------------------------------
__global__ __launch_bounds__(256) void stats_kernel(const float* __restrict__ out)
{
    const int bg = blockIdx.x;         // b*16 + g
    const int b  = bg >> 4;
    const int g  = bg & 15;
    const float* p = out + ((size_t)(b * COd + g * CPG) << 12);

    float s = 0.0f, ss = 0.0f;
    const int total = CPG * HW;        // 65536
    for (int i = threadIdx.x * 4; i < total; i += 256 * 4) {
        float4 v = *(const float4*)(p + i);
        s  += v.x + v.y + v.z + v.w;
        ss += v.x * v.x + v.y * v.y + v.z * v.z + v.w * v.w;
    }

    __shared__ float sh_s[256];
    __shared__ float sh_q[256];
    sh_s[threadIdx.x] = s;
    sh_q[threadIdx.x] = ss;
    __syncthreads();
    for (int stride = 128; stride > 0; stride >>= 1) {
        if (threadIdx.x < stride) {
            sh_s[threadIdx.x] += sh_s[threadIdx.x + stride];
            sh_q[threadIdx.x] += sh_q[threadIdx.x + stride];
        }
        __syncthreads();
    }
    if (threadIdx.x == 0) {
        const float cnt = (float)total;
        float mu  = sh_s[0] / cnt;
        float var = sh_q[0] / cnt - mu * mu;
        g_stats[bg * 2 + 0] = mu;
        g_stats[bg * 2 + 1] = rsqrtf(var + 1e-5f);
    }
}

// ---------------------------------------------------------------------------
// Kernel 4: normalize in place: out = (out - mu) * inv * gamma[o] + beta[o]
// grid: 4096 blocks of 256, one float4 per thread
// ---------------------------------------------------------------------------
__global__ __launch_bounds__(256) void norm_kernel(
    float* __restrict__ out,
    const float* __restrict__ gamma,
    const float* __restrict__ beta)
{
    const int idx = blockIdx.x * 256 + threadIdx.x;  // float4 index
    const int fi  = idx << 2;
    const int o   = (fi >> 12) & 255;
    const int b   = fi >> 20;
    const int g   = o >> 4;

    const float mu  = g_stats[(b * 16 + g) * 2 + 0];
    const float inv = g_stats[(b * 16 + g) * 2 + 1];
    const float ga  = gamma[o] * inv;
    const float be  = beta[o] - mu * ga;

    float4 v = ((const float4*)out)[idx];
    v.x = v.x * ga + be;
    v.y = v.y * ga + be;
    v.z = v.z * ga + be;
    v.w = v.w * ga + be;
    ((float4*)out)[idx] = v;
}

// ---------------------------------------------------------------------------
extern "C" void kernel_launch(void* const* d_in, const int* in_sizes, int n_in,
                              void* d_out, int out_size)
{
    const float* input  = (const float*)d_in[0];  // [4,256,64,64]
    const float* offset = (const float*)d_in[1];  // [4,18,64,64]
    const float* mask   = (const float*)d_in[2];  // [4,9,64,64]
    const float* weight = (const float*)d_in[3];  // [256,256,3,3]
    const float* bias   = (const float*)d_in[4];  // [256]
    const float* gamma  = (const float*)d_in[5];  // [256]
    const float* beta   = (const float*)d_in[6];  // [256]
    float* out = (float*)d_out;                   // [4,256,64,64]

    dim3 gs(NTOT / 256, Kd);
    sample_kernel<<<gs, 256>>>(input, offset, mask);

    dim3 gg(NTOT / BN, COd / BM);
    gemm_kernel<<<gg, 256>>>(weight, bias, out);

    stats_kernel<<<Bd * NGRP, 256>>>(out);

    norm_kernel<<<(Bd * COd * HW) / (4 * 256), 256>>>(out, gamma, beta);
}

// round 3
// speedup vs baseline: 2.0045x; 2.0045x over previous
#include <cuda_runtime.h>
#include <cuda_bf16.h>
#include <cstdint>

#define Hd   64
#define Wd   64
#define HW   4096
#define Bd   4
#define Cd   256
#define COd  256
#define KDIM 2304    // Cd * 9
#define NTOT 16384   // Bd * HW
#define NGRP 16
#define CPG  16

// GEMM tiling
#define BM 128
#define BN 128
#define BK 32
#define KCH   (KDIM / BK)      // 72 k-chunks per pass
#define NSTG  (2 * KCH)        // 144 stages: phase0 = (Ah,Al)xBh, phase1 = Ah x Bl
// smem stage layout: Ah[128][40], Al[128][40], B[32][136] (bf16, padded rows)
#define A_ROW_B   80           // 32 bf16 data + 16B pad
#define B_ROW_B   272          // 256B data + 16B pad
#define A_TILE_B  (BM * A_ROW_B)          // 10240
#define B_TILE_B  (BK * B_ROW_B)          // 8704
#define STAGE_B   (2 * A_TILE_B + B_TILE_B)   // 29184
#define SMEM_TOTAL (3 * STAGE_B)              // 87552

// im2col columns as bf16 hi/lo, layout [k=2304][n=16384]
__device__ __align__(256) __nv_bfloat16 g_colsh[(size_t)KDIM * NTOT];
__device__ __align__(256) __nv_bfloat16 g_colsl[(size_t)KDIM * NTOT];
// weights split to bf16 hi/lo, [256][2304]
__device__ __align__(256) __nv_bfloat16 g_wh[COd * KDIM];
__device__ __align__(256) __nv_bfloat16 g_wl[COd * KDIM];
// per (b, group): mean, rsqrt(var+eps)
__device__ float g_stats[Bd * NGRP * 2];

// ---------------------------------------------------------------------------
__device__ __forceinline__ uint32_t smem_u32(const void* p) {
    uint32_t a;
    asm("{ .reg .u64 t; cvta.to.shared.u64 t, %1; cvt.u32.u64 %0, t; }" : "=r"(a) : "l"(p));
    return a;
}
#define CP_ASYNC(dst, src) \
    asm volatile("cp.async.cg.shared.global [%0], [%1], 16;" :: "r"(dst), "l"(src))
#define CP_COMMIT() asm volatile("cp.async.commit_group;")
#define CP_WAIT(n)  asm volatile("cp.async.wait_group %0;" :: "n"(n))

#define LDMATRIX_X4(r0, r1, r2, r3, a) \
    asm volatile("ldmatrix.sync.aligned.m8n8.x4.shared.b16 {%0,%1,%2,%3}, [%4];" \
        : "=r"(r0), "=r"(r1), "=r"(r2), "=r"(r3) : "r"(a))
#define LDMATRIX_X4T(r0, r1, r2, r3, a) \
    asm volatile("ldmatrix.sync.aligned.m8n8.x4.trans.shared.b16 {%0,%1,%2,%3}, [%4];" \
        : "=r"(r0), "=r"(r1), "=r"(r2), "=r"(r3) : "r"(a))

#define MMA_BF16(d, a, b0v, b1v) \
    asm volatile("mma.sync.aligned.m16n8k16.row.col.f32.bf16.bf16.f32 " \
        "{%0,%1,%2,%3}, {%4,%5,%6,%7}, {%8,%9}, {%0,%1,%2,%3};" \
        : "+f"((d)[0]), "+f"((d)[1]), "+f"((d)[2]), "+f"((d)[3]) \
        : "r"((a)[0]), "r"((a)[1]), "r"((a)[2]), "r"((a)[3]), "r"(b0v), "r"(b1v))

// ---------------------------------------------------------------------------
// Kernel 0: split weights into bf16 hi/lo
// ---------------------------------------------------------------------------
__global__ __launch_bounds__(256) void wprep_kernel(const float* __restrict__ w) {
    int i = blockIdx.x * 256 + threadIdx.x;
    float v = w[i];
    __nv_bfloat16 hi = __float2bfloat16(v);
    g_wh[i] = hi;
    g_wl[i] = __float2bfloat16(v - __bfloat162float(hi));
}

// ---------------------------------------------------------------------------
// Kernel 1: deformable bilinear sampling -> bf16 hi/lo columns [k][n]
// ---------------------------------------------------------------------------
__global__ __launch_bounds__(256) void sample_kernel(
    const float* __restrict__ in, const float* __restrict__ off,
    const float* __restrict__ mask)
{
    const int n  = blockIdx.x * 256 + threadIdx.x;
    const int k  = blockIdx.y;
    const int b  = n >> 12;
    const int hw = n & 4095;
    const int h  = hw >> 6;
    const int w  = hw & 63;

    const float dy = off[((b * 18 + 2 * k)     << 12) + hw];
    const float dx = off[((b * 18 + 2 * k + 1) << 12) + hw];
    const float m  = mask[((b * 9 + k)         << 12) + hw];

    const float y = (float)h + (float)(k / 3 - 1) + dy;
    const float x = (float)w + (float)(k % 3 - 1) + dx;
    const float y0f = floorf(y), x0f = floorf(x);
    const int   y0 = (int)y0f,  x0 = (int)x0f;
    const float wy1 = y - y0f, wx1 = x - x0f;
    const float wy0 = 1.0f - wy1, wx0 = 1.0f - wx1;

    const bool vy0 = (y0 >= 0) && (y0 < Hd);
    const bool vy1 = (y0 + 1 >= 0) && (y0 + 1 < Hd);
    const bool vx0 = (x0 >= 0) && (x0 < Wd);
    const bool vx1 = (x0 + 1 >= 0) && (x0 + 1 < Wd);

    const float w00 = (vy0 && vx0) ? wy0 * wx0 * m : 0.0f;
    const float w01 = (vy0 && vx1) ? wy0 * wx1 * m : 0.0f;
    const float w10 = (vy1 && vx0) ? wy1 * wx0 * m : 0.0f;
    const float w11 = (vy1 && vx1) ? wy1 * wx1 * m : 0.0f;

    const int i00 = (vy0 && vx0) ? (y0       * Wd + x0    ) : 0;
    const int i01 = (vy0 && vx1) ? (y0       * Wd + x0 + 1) : 0;
    const int i10 = (vy1 && vx0) ? ((y0 + 1) * Wd + x0    ) : 0;
    const int i11 = (vy1 && vx1) ? ((y0 + 1) * Wd + x0 + 1) : 0;

    const float* __restrict__ p = in + (size_t)(b * Cd) * HW;
    size_t idx = (size_t)k * NTOT + n;

#pragma unroll 4
    for (int c = 0; c < Cd; ++c) {
        const float* pc = p + c * HW;
        float v = w00 * __ldg(pc + i00) + w01 * __ldg(pc + i01)
                + w10 * __ldg(pc + i10) + w11 * __ldg(pc + i11);
        __nv_bfloat16 hi = __float2bfloat16(v);
        g_colsh[idx] = hi;
        g_colsl[idx] = __float2bfloat16(v - __bfloat162float(hi));
        idx += (size_t)9 * NTOT;
    }
}

// ---------------------------------------------------------------------------
// Stage loader: cp.async one stage (Ah, Al, B) into smem buffer
// ---------------------------------------------------------------------------
__device__ __forceinline__ void load_stage(uint32_t sbuf, int s, int m0, int n0, int tid)
{
    const int phase = (s >= KCH);
    const int k0    = (phase ? s - KCH : s) * BK;
    const __nv_bfloat16* bsrc = phase ? g_colsl : g_colsh;

#pragma unroll
    for (int j = 0; j < 6; ++j) {
        const int c = tid + j * 256;
        if (c < 512) {                    // Ah: 128 rows x 4 chunks
            const int row = c >> 2, seg = c & 3;
            const __nv_bfloat16* g = g_wh + (m0 + row) * KDIM + k0 + seg * 8;
            CP_ASYNC(sbuf + row * A_ROW_B + seg * 16, g);
        } else if (c < 1024) {            // Al (only needed in phase 0)
            if (!phase) {
                const int cc = c - 512;
                const int row = cc >> 2, seg = cc & 3;
                const __nv_bfloat16* g = g_wl + (m0 + row) * KDIM + k0 + seg * 8;
                CP_ASYNC(sbuf + A_TILE_B + row * A_ROW_B + seg * 16, g);
            }
        } else {                          // B: 32 rows x 16 chunks
            const int cc = c - 1024;
            const int row = cc >> 4, seg = cc & 15;
            const __nv_bfloat16* g = bsrc + (size_t)(k0 + row) * NTOT + n0 + seg * 8;
            CP_ASYNC(sbuf + 2 * A_TILE_B + row * B_ROW_B + seg * 16, g);
        }
    }
    CP_COMMIT();
}

// ---------------------------------------------------------------------------
// Kernel 2: bf16x3 GEMM via mma.sync.  grid = (2 m-tiles, 128 n-tiles).
// out[m, n] = sum_k W[m,k] * cols[k,n] + bias[m]
// ---------------------------------------------------------------------------
__global__ __launch_bounds__(256, 2) void gemm_mma(
    const float* __restrict__ bias, float* __restrict__ out)
{
    extern __shared__ char smem[];
    const uint32_t sb = smem_u32(smem);
    const int tid = threadIdx.x;
    const int wid = tid >> 5;
    const int lid = tid & 31;
    const int wm  = wid >> 2;        // 0..1  -> 64-row warp tile
    const int wn  = wid & 3;         // 0..3  -> 32-col warp tile
    const int m0  = blockIdx.x * BM; // m-fastest for B L2 reuse
    const int n0  = blockIdx.y * BN;

    float acc[4][4][4];
#pragma unroll
    for (int i = 0; i < 4; ++i)
#pragma unroll
        for (int j = 0; j < 4; ++j)
#pragma unroll
            for (int r = 0; r < 4; ++r) acc[i][j][r] = 0.0f;

    // prologue: stages 0, 1
    load_stage(sb, 0, m0, n0, tid);
    load_stage(sb + STAGE_B, 1, m0, n0, tid);
    CP_WAIT(1);
    __syncthreads();

    // ldmatrix base addresses (lane-dependent parts)
    const uint32_t a_lane = (uint32_t)((lid & 15) * A_ROW_B + (lid >> 4) * 16);
    const uint32_t b_lane = (uint32_t)((lid & 15) * B_ROW_B + (lid >> 4) * 16);

    for (int s = 0; s < NSTG; ++s) {
        const uint32_t sbuf = sb + (uint32_t)(s % 3) * STAGE_B;
        const int phase = (s >= KCH);

        if (s + 2 < NSTG) load_stage(sb + (uint32_t)((s + 2) % 3) * STAGE_B, s + 2, m0, n0, tid);

#pragma unroll
        for (int kk = 0; kk < 2; ++kk) {
            // B fragments: 2 x ldmatrix.x4.trans covering n 0..31 of warp
            uint32_t bf[2][4];
#pragma unroll
            for (int j2 = 0; j2 < 2; ++j2) {
                const uint32_t addr = sbuf + 2 * A_TILE_B + (uint32_t)(kk * 16) * B_ROW_B
                                    + (uint32_t)((wn * 32 + j2 * 16) * 2) + b_lane;
                LDMATRIX_X4T(bf[j2][0], bf[j2][1], bf[j2][2], bf[j2][3], addr);
            }
            // Ah fragments + mma
            {
                uint32_t af[4][4];
#pragma unroll
                for (int i = 0; i < 4; ++i) {
                    const uint32_t addr = sbuf + (uint32_t)((wm * 64 + i * 16) * A_ROW_B)
                                        + (uint32_t)(kk * 32) + a_lane;
                    LDMATRIX_X4(af[i][0], af[i][1], af[i][2], af[i][3], addr);
                }
#pragma unroll
                for (int i = 0; i < 4; ++i)
#pragma unroll
                    for (int j = 0; j < 4; ++j)
                        MMA_BF16(acc[i][j], af[i], bf[j >> 1][(j & 1) * 2], bf[j >> 1][(j & 1) * 2 + 1]);
            }
            // Al fragments + mma (phase 0 only)
            if (!phase) {
                uint32_t af[4][4];
#pragma unroll
                for (int i = 0; i < 4; ++i) {
                    const uint32_t addr = sbuf + A_TILE_B + (uint32_t)((wm * 64 + i * 16) * A_ROW_B)
                                        + (uint32_t)(kk * 32) + a_lane;
                    LDMATRIX_X4(af[i][0], af[i][1], af[i][2], af[i][3], addr);
                }
#pragma unroll
                for (int i = 0; i < 4; ++i)
#pragma unroll
                    for (int j = 0; j < 4; ++j)
                        MMA_BF16(acc[i][j], af[i], bf[j >> 1][(j & 1) * 2], bf[j >> 1][(j & 1) * 2 + 1]);
            }
        }

        if (s < NSTG - 2) { CP_WAIT(1); } else { CP_WAIT(0); }
        __syncthreads();
    }

    // epilogue: d0,d1 -> (row, col..col+1); d2,d3 -> (row+8, col..col+1)
    const int b   = n0 >> 12;
    const int hwb = n0 & 4095;
#pragma unroll
    for (int i = 0; i < 4; ++i) {
        const int o_lo = m0 + wm * 64 + i * 16 + (lid >> 2);
        const float bi0 = bias[o_lo];
        const float bi1 = bias[o_lo + 8];
#pragma unroll
        for (int j = 0; j < 4; ++j) {
            const int nc = hwb + wn * 32 + j * 8 + (lid & 3) * 2;
            float2 v0 = make_float2(acc[i][j][0] + bi0, acc[i][j][1] + bi0);
            float2 v1 = make_float2(acc[i][j][2] + bi1, acc[i][j][3] + bi1);
            *(float2*)(out + (((size_t)(b * COd + o_lo))     << 12) + nc) = v0;
            *(float2*)(out + (((size_t)(b * COd + o_lo + 8)) << 12) + nc) = v1;
        }
    }
}

// ---------------------------------------------------------------------------
// Kernel 3: GroupNorm stats per (b, group)
// ---------------------------------------------------------------------------
__global__ __launch_bounds__(256) void stats_kernel(const float* __restrict__ out)
{
    const int bg = blockIdx.x;
    const int b  = bg >> 4;
    const int g  = bg & 15;
    const float* p = out + ((size_t)(b * COd + g * CPG) << 12);

    float s = 0.0f, ss = 0.0f;
    const int total = CPG * HW;
    for (int i = threadIdx.x * 4; i < total; i += 256 * 4) {
        float4 v = *(const float4*)(p + i);
        s  += v.x + v.y + v.z + v.w;
        ss += v.x * v.x + v.y * v.y + v.z * v.z + v.w * v.w;
    }
    __shared__ float sh_s[256], sh_q[256];
    sh_s[threadIdx.x] = s; sh_q[threadIdx.x] = ss;
    __syncthreads();
    for (int st = 128; st > 0; st >>= 1) {
        if (threadIdx.x < st) {
            sh_s[threadIdx.x] += sh_s[threadIdx.x + st];
            sh_q[threadIdx.x] += sh_q[threadIdx.x + st];
        }
        __syncthreads();
    }
    if (threadIdx.x == 0) {
        const float cnt = (float)total;
        float mu  = sh_s[0] / cnt;
        float var = sh_q[0] / cnt - mu * mu;
        g_stats[bg * 2 + 0] = mu;
        g_stats[bg * 2 + 1] = rsqrtf(var + 1e-5f);
    }
}

// ---------------------------------------------------------------------------
// Kernel 4: normalize in place
// ---------------------------------------------------------------------------
__global__ __launch_bounds__(256) void norm_kernel(
    float* __restrict__ out, const float* __restrict__ gamma,
    const float* __restrict__ beta)
{
    const int idx = blockIdx.x * 256 + threadIdx.x;
    const int fi  = idx << 2;
    const int o   = (fi >> 12) & 255;
    const int b   = fi >> 20;
    const int g   = o >> 4;

    const float mu  = g_stats[(b * 16 + g) * 2 + 0];
    const float inv = g_stats[(b * 16 + g) * 2 + 1];
    const float ga  = gamma[o] * inv;
    const float be  = beta[o] - mu * ga;

    float4 v = ((const float4*)out)[idx];
    v.x = v.x * ga + be; v.y = v.y * ga + be;
    v.z = v.z * ga + be; v.w = v.w * ga + be;
    ((float4*)out)[idx] = v;
}

// ---------------------------------------------------------------------------
extern "C" void kernel_launch(void* const* d_in, const int* in_sizes, int n_in,
                              void* d_out, int out_size)
{
    const float* input  = (const float*)d_in[0];
    const float* offset = (const float*)d_in[1];
    const float* mask   = (const float*)d_in[2];
    const float* weight = (const float*)d_in[3];
    const float* bias   = (const float*)d_in[4];
    const float* gamma  = (const float*)d_in[5];
    const float* beta   = (const float*)d_in[6];
    float* out = (float*)d_out;

    cudaFuncSetAttribute(gemm_mma, cudaFuncAttributeMaxDynamicSharedMemorySize, SMEM_TOTAL);

    wprep_kernel<<<COd * KDIM / 256, 256>>>(weight);

    dim3 gs(NTOT / 256, 9);
    sample_kernel<<<gs, 256>>>(input, offset, mask);

    dim3 gg(COd / BM, NTOT / BN);   // m fastest -> B-tile L2 reuse
    gemm_mma<<<gg, 256, SMEM_TOTAL>>>(bias, out);

    stats_kernel<<<Bd * NGRP, 256>>>(out);

    norm_kernel<<<(Bd * COd * HW) / (4 * 256), 256>>>(out, gamma, beta);
}